// round 3
// baseline (speedup 1.0000x reference)
#include <cuda_runtime.h>
#include <cuda_bf16.h>
#include <cstdint>

#define NPROMPT 20

// Scratch: per-(b,l) source selector. -1 => copy from input_embeds,
// r in [0, NPROMPT) => copy prompt row r. Sized for up to 65536 rows (B*L).
__device__ int g_rank[1 << 16];
// 1 if sample_id buffer is int64 (little-endian), 0 if int32.
__device__ int g_sid64;

// ---------------------------------------------------------------------------
// Kernel 0: probe sample_id dtype. Reads only B int32 words, which is within
// bounds whether the buffer holds B int32s or B int64s.
// int64 case (ids < 2^31): every odd word (hi half) is 0.
// int32 case: odd words are random ids in [0, N_SAMPLES) -> ~never all zero.
// ---------------------------------------------------------------------------
__global__ void probe_sid_kernel(const int* __restrict__ sid_words, int B) {
    if (threadIdx.x == 0 && blockIdx.x == 0) {
        int all_hi_zero = 1;
        for (int i = 1; i < B; i += 2) {
            if (sid_words[i] != 0) { all_hi_zero = 0; break; }
        }
        g_sid64 = all_hi_zero;
    }
}

// ---------------------------------------------------------------------------
// Kernel 1: per-batch-row pad-rank scan + mask output.
// One block per batch row; blockDim covers L (L <= 1024).
// ---------------------------------------------------------------------------
__global__ void rank_mask_scan_kernel(const int* __restrict__ mask, int L,
                                      float* __restrict__ mask_out) {
    int b = blockIdx.x;
    int t = threadIdx.x;
    int m = 0, pad = 0;
    if (t < L) {
        m = mask[(size_t)b * L + t];
        pad = (m == 0);
    }
    unsigned bal = __ballot_sync(0xFFFFFFFFu, pad);
    int lane = t & 31;
    int warp = t >> 5;

    __shared__ int wtot[32];
    if (lane == 0) wtot[warp] = __popc(bal);
    __syncthreads();

    int prefix = 0;
    for (int w = 0; w < warp; ++w) prefix += wtot[w];
    int rank = prefix + __popc(bal & ((1u << lane) - 1u));

    if (t < L) {
        int take = (pad && rank < NPROMPT) ? 1 : 0;
        g_rank[(size_t)b * L + t] = take ? rank : -1;
        if (mask_out) mask_out[(size_t)b * L + t] = take ? 1.0f : (float)m;
    }
}

// Serial fallback for L > 1024 (not expected here).
__global__ void rank_mask_serial_kernel(const int* __restrict__ mask, int B, int L,
                                        float* __restrict__ mask_out) {
    int b = blockIdx.x * blockDim.x + threadIdx.x;
    if (b >= B) return;
    int cnt = 0;
    for (int l = 0; l < L; ++l) {
        int m = mask[(size_t)b * L + l];
        int is_pad = (m == 0);
        int take = is_pad && (cnt < NPROMPT);
        g_rank[(size_t)b * L + l] = take ? cnt : -1;
        if (mask_out) mask_out[(size_t)b * L + l] = take ? 1.0f : (float)m;
        cnt += is_pad;
    }
}

// ---------------------------------------------------------------------------
// Kernel 2: streaming copy with per-row source select, float4 vectorized.
// One block per (b,l) position. All threads in a block share the same rank
// -> zero divergence; g_rank[row] is a single broadcast load.
// ---------------------------------------------------------------------------
__global__ void splice_copy_vec4_kernel(const float4* __restrict__ in,
                                        const float4* __restrict__ prompts,
                                        const void* __restrict__ sid_raw,
                                        float4* __restrict__ out,
                                        int L, int Dv, long long NS) {
    int row = blockIdx.x;            // b*L + l
    int r = g_rank[row];
    size_t base = (size_t)row * Dv;

    if (r < 0) {
        for (int c = threadIdx.x; c < Dv; c += blockDim.x) {
            out[base + c] = in[base + c];
        }
    } else {
        int b = row / L;
        long long s = g_sid64 ? ((const long long*)sid_raw)[b]
                              : (long long)((const int*)sid_raw)[b];
        if (s < 0) s = 0;
        if (s >= NS) s = NS - 1;
        size_t pbase = ((size_t)s * NPROMPT + r) * (size_t)Dv;
        for (int c = threadIdx.x; c < Dv; c += blockDim.x) {
            out[base + c] = prompts[pbase + c];
        }
    }
}

// Scalar fallback for D % 4 != 0 (not expected: D=768).
__global__ void splice_copy_scalar_kernel(const float* __restrict__ in,
                                          const float* __restrict__ prompts,
                                          const void* __restrict__ sid_raw,
                                          float* __restrict__ out,
                                          int L, int D, long long NS) {
    int row = blockIdx.x;
    int r = g_rank[row];
    size_t base = (size_t)row * D;
    if (r < 0) {
        for (int c = threadIdx.x; c < D; c += blockDim.x) {
            out[base + c] = in[base + c];
        }
    } else {
        int b = row / L;
        long long s = g_sid64 ? ((const long long*)sid_raw)[b]
                              : (long long)((const int*)sid_raw)[b];
        if (s < 0) s = 0;
        if (s >= NS) s = NS - 1;
        size_t pbase = ((size_t)s * NPROMPT + r) * (size_t)D;
        for (int c = threadIdx.x; c < D; c += blockDim.x) {
            out[base + c] = prompts[pbase + c];
        }
    }
}

extern "C" void kernel_launch(void* const* d_in, const int* in_sizes, int n_in,
                              void* d_out, int out_size) {
    // Bind inputs by size rank (robust to ordering):
    //   smallest        -> sample_id_tensor [B]
    //   2nd smallest    -> attention_mask   [B*L]
    //   2nd largest     -> input_embeds     [B*L*D]
    //   largest         -> prompt_embeddings [NS*NPROMPT*D]
    int idx[4] = {0, 1, 2, 3};
    // simple sort of 4 indices by in_sizes ascending
    for (int i = 0; i < 4; ++i)
        for (int j = i + 1; j < 4; ++j)
            if (in_sizes[idx[j]] < in_sizes[idx[i]]) {
                int t = idx[i]; idx[i] = idx[j]; idx[j] = t;
            }
    const void*  sid     = d_in[idx[0]];
    const int*   mask    = (const int*)d_in[idx[1]];
    const float* embeds  = (const float*)d_in[idx[2]];
    const float* prompts = (const float*)d_in[idx[3]];

    int B  = in_sizes[idx[0]];
    int BL = in_sizes[idx[1]];
    int L  = BL / B;
    long long D  = (long long)in_sizes[idx[2]] / BL;
    long long NS = (long long)in_sizes[idx[3]] / (NPROMPT * D);

    float* out = (float*)d_out;
    size_t embed_elems = (size_t)BL * (size_t)D;
    // Tuple output: embeds followed by mask, if the buffer has room for both.
    float* mask_out = ((size_t)out_size >= embed_elems + (size_t)BL)
                          ? out + embed_elems
                          : nullptr;

    // --- Kernel 0: sid dtype probe ---
    probe_sid_kernel<<<1, 32>>>((const int*)sid, B);

    // --- Kernel 1: pad ranks + mask output ---
    if (L <= 1024) {
        int threads = ((L + 31) / 32) * 32;
        rank_mask_scan_kernel<<<B, threads>>>(mask, L, mask_out);
    } else {
        int threads = 128;
        int blocks = (B + threads - 1) / threads;
        rank_mask_serial_kernel<<<blocks, threads>>>(mask, B, L, mask_out);
    }

    // --- Kernel 2: streaming splice copy ---
    if ((D & 3) == 0) {
        int Dv = (int)(D >> 2);
        int threads = Dv < 1024 ? Dv : 1024;
        threads = ((threads + 31) / 32) * 32;
        if (threads > 1024) threads = 1024;
        splice_copy_vec4_kernel<<<BL, threads>>>(
            (const float4*)embeds, (const float4*)prompts, sid,
            (float4*)out, L, Dv, NS);
    } else {
        int threads = (int)(D < 1024 ? ((D + 31) / 32) * 32 : 1024);
        splice_copy_scalar_kernel<<<BL, threads>>>(
            embeds, prompts, sid, out, (int)L, (int)D, NS);
    }
}